// round 2
// baseline (speedup 1.0000x reference)
#include <cuda_runtime.h>

// DWHT (buggy torch in-place semantics) + channel shuffle, fully fused.
//
// x: (64, 256, 28, 28) f32  ->  out: (64, 512, 28, 28) f32
//
// One pass F on a 512-vector v:
//   F[i]      = v[2i]+v[2i+1]                      i in [0,256)
//   F[256+c]  = v[4c]+v[4c+1]-v[4c+2]-v[4c+3]      c in [0,128)
//   F[384+k]  = v[256+2k]-v[256+2k+1]              k in [0,128)
// 8 passes = (F o F)^4.  G = F o F has the property that every output
// depends only on ONE aligned 16-channel input chunk:
//   chunk j (all j in [0,32)), w[0..15] = v[16j..16j+16):
//     A   : out[4j+q]       = w4q+w4q1+w4q2+w4q3                       q<4
//     B   : out[128+2j+r]   = ++--++--  (8-run at 8r)                  r<2
//     D   : out[256+2j+r]   = ++++----                                 r<2
//     E   : out[320+j]      = ++--++-- --++--++   (16-run)
//     G2a : out[384+2j+r]   = ++----++                                 r<2
//   chunk j >= 16 additionally:
//     C   : out[128+4j+q]   = +-+-      (4-run at 4q)                  q<4
//     F2  : out[320+2j+r]   = +-+--+-+  (8-run at 8r)                  r<2
//     G2b : out[384+4j+q]   = +--+      (4-run at 4q)                  q<4
// Final channel shuffle (groups=8): y-channel ch -> out channel
//   ((ch & 63) << 3) | (ch >> 6).

#define NPIX   16      // pixels per block (784 = 49*16, so one image per block)
#define SPITCH 17      // smem pitch in floats (odd -> read conflict-free)

__device__ __forceinline__ void butterfly2(const float wl[16], const float wh[16],
                                           float o[32]) {
    int n = 0;
#pragma unroll
    for (int q = 0; q < 4; q++)
        o[n++] = wl[4*q+0] + wl[4*q+1] + wl[4*q+2] + wl[4*q+3];            // A (low)
#pragma unroll
    for (int r = 0; r < 2; r++) {
        const float a0 = wl[8*r+0], a1 = wl[8*r+1], a2 = wl[8*r+2], a3 = wl[8*r+3];
        const float a4 = wl[8*r+4], a5 = wl[8*r+5], a6 = wl[8*r+6], a7 = wl[8*r+7];
        o[n++] = a0+a1-a2-a3+a4+a5-a6-a7;                                  // B (low)
        o[n++] = a0+a1+a2+a3-a4-a5-a6-a7;                                  // D (low)
        o[n++] = a0+a1-a2-a3-a4-a5+a6+a7;                                  // G2a (low)
    }
    o[n++] = wl[0]+wl[1]-wl[2]-wl[3]+wl[4]+wl[5]-wl[6]-wl[7]
            -wl[8]-wl[9]+wl[10]+wl[11]-wl[12]-wl[13]+wl[14]+wl[15];        // E (low)
#pragma unroll
    for (int q = 0; q < 4; q++) {
        const float b0 = wh[4*q+0], b1 = wh[4*q+1], b2 = wh[4*q+2], b3 = wh[4*q+3];
        o[n++] = b0+b1+b2+b3;                                              // A (high)
        o[n++] = b0-b1+b2-b3;                                              // C
        o[n++] = b0-b1-b2+b3;                                              // G2b
    }
#pragma unroll
    for (int r = 0; r < 2; r++) {
        const float b0 = wh[8*r+0], b1 = wh[8*r+1], b2 = wh[8*r+2], b3 = wh[8*r+3];
        const float b4 = wh[8*r+4], b5 = wh[8*r+5], b6 = wh[8*r+6], b7 = wh[8*r+7];
        o[n++] = b0+b1-b2-b3+b4+b5-b6-b7;                                  // B (high)
        o[n++] = b0+b1+b2+b3-b4-b5-b6-b7;                                  // D (high)
        o[n++] = b0+b1-b2-b3-b4-b5+b6+b7;                                  // G2a (high)
        o[n++] = b0-b1+b2-b3-b4+b5-b6+b7;                                  // F2
    }
    o[n++] = wh[0]+wh[1]-wh[2]-wh[3]+wh[4]+wh[5]-wh[6]-wh[7]
            -wh[8]-wh[9]+wh[10]+wh[11]-wh[12]-wh[13]+wh[14]+wh[15];        // E (high)
}

// Emit output channel indices in EXACTLY the same canonical order as butterfly2
// fills o[].
template <typename PUT>
__device__ __forceinline__ void emit_indices(int jl, PUT put) {
    const int jh = jl + 16;
    int n = 0;
#pragma unroll
    for (int q = 0; q < 4; q++) put(n++, 4*jl + q);
#pragma unroll
    for (int r = 0; r < 2; r++) {
        put(n++, 128 + 2*jl + r);
        put(n++, 256 + 2*jl + r);
        put(n++, 384 + 2*jl + r);
    }
    put(n++, 320 + jl);
#pragma unroll
    for (int q = 0; q < 4; q++) {
        put(n++,   4*jh + q);
        put(n++, 128 + 4*jh + q);
        put(n++, 384 + 4*jh + q);
    }
#pragma unroll
    for (int r = 0; r < 2; r++) {
        put(n++, 128 + 2*jh + r);
        put(n++, 256 + 2*jh + r);
        put(n++, 384 + 2*jh + r);
        put(n++, 320 + 2*jh + r);
    }
    put(n++, 320 + jh);
}

__global__ __launch_bounds__(256)
void dwht_kernel(const float* __restrict__ x, float* __restrict__ out) {
    __shared__ float s[512 * SPITCH];

    const int tid = threadIdx.x;
    const int p   = tid & (NPIX - 1);   // pixel within block  [0,16)
    const int jl  = tid >> 4;           // lower chunk id      [0,16)
    const int jh  = jl + 16;

    const int b    = blockIdx.x / 49;
    const int hw   = (blockIdx.x % 49) * NPIX + p;
    const float* xp = x   + (size_t)b * (256 * 784) + hw;
    float*       op = out + (size_t)b * (512 * 784) + hw;

    float wl[16], wh[16], o[32];

    // ---- stage 1: global load (upper 256 channels are the zero pad) ----
#pragma unroll
    for (int m = 0; m < 16; m++) wl[m] = xp[(16 * jl + m) * 784];
#pragma unroll
    for (int m = 0; m < 16; m++) wh[m] = 0.0f;

    butterfly2(wl, wh, o);
    emit_indices(jl, [&](int n, int idx) { s[idx * SPITCH + p] = o[n]; });
    __syncthreads();

    // ---- stages 2 & 3: smem -> registers -> smem ----
#pragma unroll
    for (int st = 0; st < 2; st++) {
#pragma unroll
        for (int m = 0; m < 16; m++) wl[m] = s[(16 * jl + m) * SPITCH + p];
#pragma unroll
        for (int m = 0; m < 16; m++) wh[m] = s[(16 * jh + m) * SPITCH + p];
        butterfly2(wl, wh, o);
        __syncthreads();   // all reads done before anyone overwrites
        emit_indices(jl, [&](int n, int idx) { s[idx * SPITCH + p] = o[n]; });
        __syncthreads();
    }

    // ---- stage 4: smem -> registers -> shuffled global store ----
#pragma unroll
    for (int m = 0; m < 16; m++) wl[m] = s[(16 * jl + m) * SPITCH + p];
#pragma unroll
    for (int m = 0; m < 16; m++) wh[m] = s[(16 * jh + m) * SPITCH + p];
    butterfly2(wl, wh, o);
    emit_indices(jl, [&](int n, int idx) {
        const int c = ((idx & 63) << 3) | (idx >> 6);   // groups=8 channel shuffle
        op[c * 784] = o[n];
    });
}

extern "C" void kernel_launch(void* const* d_in, const int* in_sizes, int n_in,
                              void* d_out, int out_size) {
    const float* x = (const float*)d_in[0];
    float* out = (float*)d_out;
    // 64 images * 49 pixel-tiles of 16 pixels
    dwht_kernel<<<64 * 49, 256>>>(x, out);
}

// round 3
// speedup vs baseline: 1.1148x; 1.1148x over previous
#include <cuda_runtime.h>

// DWHT (buggy torch in-place semantics) + channel shuffle, fully fused.
//
// x: (64, 256, 28, 28) f32  ->  out: (64, 512, 28, 28) f32
//
// 8 butterfly passes = (F o F)^4 where G = F o F maps each aligned 16-channel
// input chunk to a fixed set of 16/21 outputs with +-1 signs (see butterfly2 /
// emit_indices). Final channel shuffle (groups=8): ch -> ((ch&63)<<3)|(ch>>6).
//
// Round-2 geometry: warp = 32 pixels x 1 chunk-lane. Every SMEM access has a
// fixed channel across the warp and p=0..31 across lanes -> ALL LDS/STS are
// bank-conflict-free with zero padding. s[512][32] = 64KB dynamic smem.

#define NPIX 32

__device__ __forceinline__ void butterfly2(const float wl[16], const float wh[16],
                                           float o[32]) {
    int n = 0;
#pragma unroll
    for (int q = 0; q < 4; q++)
        o[n++] = wl[4*q+0] + wl[4*q+1] + wl[4*q+2] + wl[4*q+3];            // A (low)
#pragma unroll
    for (int r = 0; r < 2; r++) {
        const float a0 = wl[8*r+0], a1 = wl[8*r+1], a2 = wl[8*r+2], a3 = wl[8*r+3];
        const float a4 = wl[8*r+4], a5 = wl[8*r+5], a6 = wl[8*r+6], a7 = wl[8*r+7];
        o[n++] = a0+a1-a2-a3+a4+a5-a6-a7;                                  // B (low)
        o[n++] = a0+a1+a2+a3-a4-a5-a6-a7;                                  // D (low)
        o[n++] = a0+a1-a2-a3-a4-a5+a6+a7;                                  // G2a (low)
    }
    o[n++] = wl[0]+wl[1]-wl[2]-wl[3]+wl[4]+wl[5]-wl[6]-wl[7]
            -wl[8]-wl[9]+wl[10]+wl[11]-wl[12]-wl[13]+wl[14]+wl[15];        // E (low)
#pragma unroll
    for (int q = 0; q < 4; q++) {
        const float b0 = wh[4*q+0], b1 = wh[4*q+1], b2 = wh[4*q+2], b3 = wh[4*q+3];
        o[n++] = b0+b1+b2+b3;                                              // A (high)
        o[n++] = b0-b1+b2-b3;                                              // C
        o[n++] = b0-b1-b2+b3;                                              // G2b
    }
#pragma unroll
    for (int r = 0; r < 2; r++) {
        const float b0 = wh[8*r+0], b1 = wh[8*r+1], b2 = wh[8*r+2], b3 = wh[8*r+3];
        const float b4 = wh[8*r+4], b5 = wh[8*r+5], b6 = wh[8*r+6], b7 = wh[8*r+7];
        o[n++] = b0+b1-b2-b3+b4+b5-b6-b7;                                  // B (high)
        o[n++] = b0+b1+b2+b3-b4-b5-b6-b7;                                  // D (high)
        o[n++] = b0+b1-b2-b3-b4-b5+b6+b7;                                  // G2a (high)
        o[n++] = b0-b1+b2-b3-b4+b5-b6+b7;                                  // F2
    }
    o[n++] = wh[0]+wh[1]-wh[2]-wh[3]+wh[4]+wh[5]-wh[6]-wh[7]
            -wh[8]-wh[9]+wh[10]+wh[11]-wh[12]-wh[13]+wh[14]+wh[15];        // E (high)
}

// Emit output channel indices in EXACTLY the same canonical order as butterfly2
// fills o[].
template <typename PUT>
__device__ __forceinline__ void emit_indices(int jl, PUT put) {
    const int jh = jl + 16;
    int n = 0;
#pragma unroll
    for (int q = 0; q < 4; q++) put(n++, 4*jl + q);
#pragma unroll
    for (int r = 0; r < 2; r++) {
        put(n++, 128 + 2*jl + r);
        put(n++, 256 + 2*jl + r);
        put(n++, 384 + 2*jl + r);
    }
    put(n++, 320 + jl);
#pragma unroll
    for (int q = 0; q < 4; q++) {
        put(n++,   4*jh + q);
        put(n++, 128 + 4*jh + q);
        put(n++, 384 + 4*jh + q);
    }
#pragma unroll
    for (int r = 0; r < 2; r++) {
        put(n++, 128 + 2*jh + r);
        put(n++, 256 + 2*jh + r);
        put(n++, 384 + 2*jh + r);
        put(n++, 320 + 2*jh + r);
    }
    put(n++, 320 + jh);
}

__global__ __launch_bounds__(512)
void dwht_kernel(const float* __restrict__ x, float* __restrict__ out) {
    extern __shared__ float s[];   // [512][NPIX] = 64 KB

    const int tid = threadIdx.x;
    const int p   = tid & (NPIX - 1);   // pixel lane within warp   [0,32)
    const int jl  = tid >> 5;           // chunk pair id = warp id  [0,16)
    const int jh  = jl + 16;

    const int b    = blockIdx.x / 25;
    const int hw   = (blockIdx.x % 25) * NPIX + p;
    const bool valid = (hw < 784);
    const float* xp = x   + (size_t)b * (256 * 784) + hw;
    float*       op = out + (size_t)b * (512 * 784) + hw;

    float wl[16], wh[16], o[32];

    // ---- stage 1: global load (upper 256 channels are the zero pad) ----
#pragma unroll
    for (int m = 0; m < 16; m++) wl[m] = valid ? xp[(16 * jl + m) * 784] : 0.0f;
#pragma unroll
    for (int m = 0; m < 16; m++) wh[m] = 0.0f;

    butterfly2(wl, wh, o);
    emit_indices(jl, [&](int n, int idx) { s[idx * NPIX + p] = o[n]; });
    __syncthreads();

    // ---- stages 2 & 3: smem -> registers -> smem ----
#pragma unroll
    for (int st = 0; st < 2; st++) {
#pragma unroll
        for (int m = 0; m < 16; m++) wl[m] = s[(16 * jl + m) * NPIX + p];
#pragma unroll
        for (int m = 0; m < 16; m++) wh[m] = s[(16 * jh + m) * NPIX + p];
        butterfly2(wl, wh, o);
        __syncthreads();   // all reads done before anyone overwrites
        emit_indices(jl, [&](int n, int idx) { s[idx * NPIX + p] = o[n]; });
        __syncthreads();
    }

    // ---- stage 4: smem -> registers -> shuffled global store ----
#pragma unroll
    for (int m = 0; m < 16; m++) wl[m] = s[(16 * jl + m) * NPIX + p];
#pragma unroll
    for (int m = 0; m < 16; m++) wh[m] = s[(16 * jh + m) * NPIX + p];
    butterfly2(wl, wh, o);
    if (valid) {
        emit_indices(jl, [&](int n, int idx) {
            const int c = ((idx & 63) << 3) | (idx >> 6);   // groups=8 shuffle
            op[c * 784] = o[n];
        });
    }
}

extern "C" void kernel_launch(void* const* d_in, const int* in_sizes, int n_in,
                              void* d_out, int out_size) {
    const float* x = (const float*)d_in[0];
    float* out = (float*)d_out;
    const int smem = 512 * NPIX * sizeof(float);   // 64 KB
    static bool attr_set = false;                  // idempotent host-side attr
    if (!attr_set) {
        cudaFuncSetAttribute(dwht_kernel,
                             cudaFuncAttributeMaxDynamicSharedMemorySize, smem);
        attr_set = true;
    }
    // 64 images * 25 pixel-tiles of 32 (last tile predicated: 784 = 24*32+16)
    dwht_kernel<<<64 * 25, 512, smem>>>(x, out);
}